// round 15
// baseline (speedup 1.0000x reference)
#include <cuda_runtime.h>
#include <cuda_fp16.h>
#include <cstdint>

#define N_NODES 100000
#define N_EDGES 1600000
#define D 128
#define N_PAD 102400   // 100 blocks * 1024 ints, zero-padded tail

// Scratch (no cudaMalloc allowed). g_cnt/g_deg are zero at entry of every
// call: BSS init covers call 1, the trailing zero_kernel covers the rest.
__device__ __align__(16) __half2 g_h[(size_t)N_NODES * (D / 2)];  // feats, fp16
__device__ __align__(16) int   g_deg[N_NODES];
__device__ __align__(16) float g_dis[N_NODES];
__device__ __align__(16) int   g_cnt[N_PAD];
__device__ __align__(16) int   g_off[N_PAD + 4];
__device__ __align__(16) int   g_cursor[N_PAD];
__device__ __align__(16) int   g_bucket[N_EDGES];
__device__ __align__(16) int   g_bsum[128];

// ---------------- zero counters (runs at END of call, for the next one) ----
__global__ __launch_bounds__(256) void zero_kernel()
{
    int i = blockIdx.x * 256 + threadIdx.x;
    if (i < N_PAD) g_cnt[i] = 0;
    if (i < N_NODES) g_deg[i] = 0;
}

// ---------------- fused histogram: deg over src, cnt over dst --------------
__global__ __launch_bounds__(256) void hist_kernel(const int* __restrict__ ei)
{
    int e = blockIdx.x * 256 + threadIdx.x;
    if (e < N_EDGES) {
        atomicAdd(&g_deg[ei[e]], 1);
        atomicAdd(&g_cnt[ei[N_EDGES + e]], 1);
    }
}

// ---------------- dis = rsqrt(deg + 1 self loop) ----------------
__global__ __launch_bounds__(256) void dis_kernel()
{
    int i = blockIdx.x * 256 + threadIdx.x;
    if (i < N_NODES) {
        g_dis[i] = rsqrtf((float)(g_deg[i] + 1));
    }
}

// ---------------- 2-phase exclusive scan over g_cnt ------------------------
// Phase 1: 100 blocks x 256 thr; each block sums 1024 ints -> g_bsum[blk]
__global__ __launch_bounds__(256) void scan_p1()
{
    __shared__ int wsum[8];
    const int tid = threadIdx.x;
    int4 v = reinterpret_cast<const int4*>(g_cnt)[blockIdx.x * 256 + tid];
    int s = v.x + v.y + v.z + v.w;
#pragma unroll
    for (int o = 16; o > 0; o >>= 1)
        s += __shfl_down_sync(0xffffffffu, s, o);
    if ((tid & 31) == 0) wsum[tid >> 5] = s;
    __syncthreads();
    if (tid < 8) {
        int t = wsum[tid];
#pragma unroll
        for (int o = 4; o > 0; o >>= 1)
            t += __shfl_down_sync(0xffu, t, o);
        if (tid == 0) g_bsum[blockIdx.x] = t;
    }
}

// Phase 2: local scan + inline block-base reduction over g_bsum
__global__ __launch_bounds__(256) void scan_p3()
{
    __shared__ int wbase[8];
    __shared__ int red[4];
    const int tid  = threadIdx.x;
    const int lane = tid & 31;
    const int wid  = tid >> 5;
    const int gi   = blockIdx.x * 256 + tid;
    const unsigned FULL = 0xffffffffu;

    int4 v = reinterpret_cast<const int4*>(g_cnt)[gi];
    int tot = v.x + v.y + v.z + v.w;

    // warp inclusive scan of per-thread totals
    int incl = tot;
#pragma unroll
    for (int o = 1; o < 32; o <<= 1) {
        int t = __shfl_up_sync(FULL, incl, o);
        if (lane >= o) incl += t;
    }
    if (lane == 31) wbase[wid] = incl;

    // block base = sum of g_bsum[k] for k < blockIdx.x (first 128 threads)
    int r = 0;
    if (tid < 128) r = (tid < blockIdx.x) ? g_bsum[tid] : 0;
#pragma unroll
    for (int o = 16; o > 0; o >>= 1)
        r += __shfl_down_sync(FULL, r, o);
    if (tid < 128 && lane == 0) red[wid] = r;
    __syncthreads();

    if (tid < 8) {
        int t = wbase[tid];
        int e = 0;
        for (int k = 0; k < 8; k++) {
            int vk = __shfl_sync(0xffu, t, k);
            if (tid > k) e += vk;
        }
        wbase[tid] = e;
    }
    __syncthreads();

    int base = (red[0] + red[1] + red[2] + red[3]) + wbase[wid] + (incl - tot);
    int4 o;
    o.x = base;
    o.y = base + v.x;
    o.z = base + v.x + v.y;
    o.w = base + v.x + v.y + v.z;
    reinterpret_cast<int4*>(g_off)[gi]    = o;
    reinterpret_cast<int4*>(g_cursor)[gi] = o;
}

// ---------------- tf32 helpers ----------------
__device__ __forceinline__ unsigned f2tf32(float f) {
    unsigned u;
    asm("cvt.rna.tf32.f32 %0, %1;" : "=r"(u) : "f"(f));
    return u;
}
__device__ __forceinline__ void mma_tf32(
    float& d0, float& d1, float& d2, float& d3,
    unsigned a0, unsigned a1, unsigned a2, unsigned a3,
    unsigned b0, unsigned b1)
{
    asm volatile(
        "mma.sync.aligned.m16n8k8.row.col.f32.tf32.tf32.f32 "
        "{%0,%1,%2,%3}, {%4,%5,%6,%7}, {%8,%9}, {%0,%1,%2,%3};"
        : "+f"(d0), "+f"(d1), "+f"(d2), "+f"(d3)
        : "r"(a0), "r"(a1), "r"(a2), "r"(a3), "r"(b0), "r"(b1));
}

// ---------------- GEMM via tf32 tensor cores -> fp16 raw h ------------------
#define KC 64
#define XS(r, k) smem_u[(r) * 68 + (k)]
#define WS(n, k) smem_u[128 * 68 + (n) * 68 + (k)]

__global__ __launch_bounds__(256, 2) void gemm_mma_kernel(
    const float* __restrict__ x, const float* __restrict__ W,
    const float* __restrict__ b)
{
    extern __shared__ unsigned smem_u[];   // 69632 B

    const int tid  = threadIdx.x;
    const int lane = tid & 31;
    const int warp = tid >> 5;
    const int r    = lane >> 2;
    const int c    = lane & 3;
    const int lrow = warp * 16;
    const int m0   = blockIdx.x * 128;

    float acc[16][4];
#pragma unroll
    for (int t = 0; t < 16; t++)
#pragma unroll
        for (int j = 0; j < 4; j++) acc[t][j] = 0.f;

#pragma unroll
    for (int chunk = 0; chunk < 2; chunk++) {
        const int kc = chunk * KC;
#pragma unroll
        for (int i = 0; i < 8; i++) {
            int f = tid + i * 256;
            int row = f >> 4;
            int kq  = f & 15;
            int grow = m0 + row;
            if (grow >= N_NODES) grow = N_NODES - 1;
            float4 xv = *reinterpret_cast<const float4*>(&x[(size_t)grow * D + kc + kq * 4]);
            uint4 xu = make_uint4(f2tf32(xv.x), f2tf32(xv.y), f2tf32(xv.z), f2tf32(xv.w));
            *reinterpret_cast<uint4*>(&XS(row, kq * 4)) = xu;
            float4 wv = *reinterpret_cast<const float4*>(&W[(size_t)row * D + kc + kq * 4]);
            uint4 wu = make_uint4(f2tf32(wv.x), f2tf32(wv.y), f2tf32(wv.z), f2tf32(wv.w));
            *reinterpret_cast<uint4*>(&WS(row, kq * 4)) = wu;
        }
        __syncthreads();

#pragma unroll
        for (int s = 0; s < 8; s++) {
            unsigned a0 = XS(lrow + r,     s * 8 + c);
            unsigned a1 = XS(lrow + r + 8, s * 8 + c);
            unsigned a2 = XS(lrow + r,     s * 8 + c + 4);
            unsigned a3 = XS(lrow + r + 8, s * 8 + c + 4);
#pragma unroll
            for (int t = 0; t < 16; t++) {
                unsigned b0 = WS(t * 8 + r, s * 8 + c);
                unsigned b1 = WS(t * 8 + r, s * 8 + c + 4);
                mma_tf32(acc[t][0], acc[t][1], acc[t][2], acc[t][3],
                         a0, a1, a2, a3, b0, b1);
            }
        }
        __syncthreads();
    }

    // epilogue: fp16 raw h (dis applied later, in place)
    const int row_a = m0 + lrow + r;
    const int row_b = row_a + 8;
#pragma unroll
    for (int t = 0; t < 16; t++) {
        int col0 = t * 8 + c * 2;
        float2 bias = *reinterpret_cast<const float2*>(&b[col0]);
        if (row_a < N_NODES) {
            g_h[(size_t)row_a * 64 + t * 4 + c] =
                __floats2half2_rn(acc[t][0] + bias.x, acc[t][1] + bias.y);
        }
        if (row_b < N_NODES) {
            g_h[(size_t)row_b * 64 + t * 4 + c] =
                __floats2half2_rn(acc[t][2] + bias.x, acc[t][3] + bias.y);
        }
    }
}

// ---------------- scale (in place): g_h[row] *= dis[row] --------------------
// A row is 128 halfs = 256 B = 16 uint4  -> N_NODES*16 threads.
__global__ __launch_bounds__(256) void scale_kernel()
{
    int gid = blockIdx.x * 256 + threadIdx.x;
    int row = gid >> 4, q = gid & 15;           // q: uint4 index within row
    if (row >= N_NODES) return;
    float dd = g_dis[row];
    uint4* p = reinterpret_cast<uint4*>(g_h) + (size_t)row * 16 + q;
    uint4 u = *p;
    __half2* hp = reinterpret_cast<__half2*>(&u);
#pragma unroll
    for (int k = 0; k < 4; k++) {
        float2 f = __half22float2(hp[k]);
        hp[k] = __floats2half2_rn(dd * f.x, dd * f.y);
    }
    *p = u;
}

// ---------------- bucket fill: group src ids by dst -------------------------
__global__ __launch_bounds__(256) void fill_kernel(const int* __restrict__ ei)
{
    int e = blockIdx.x * 256 + threadIdx.x;
    if (e < N_EDGES) {
        int src = ei[e];
        int dst = ei[N_EDGES + e];
        int pos = atomicAdd(&g_cursor[dst], 1);
        g_bucket[pos] = src;
    }
}

// ---------------- gather: warp per node, warp per edge, 16-deep batches -----
#define ACC2(U) do {                                                          \
    float2 f_;                                                                \
    f_ = __half22float2(*reinterpret_cast<__half2*>(&(U).x)); a0.x += f_.x; a0.y += f_.y; \
    f_ = __half22float2(*reinterpret_cast<__half2*>(&(U).y)); a1.x += f_.x; a1.y += f_.y; \
} while (0)

__global__ __launch_bounds__(256) void gather_kernel(float* __restrict__ out)
{
    const int node = blockIdx.x * 8 + (threadIdx.x >> 5);
    if (node >= N_NODES) return;
    const int lane = threadIdx.x & 31;
    const unsigned FULL = 0xffffffffu;

    const int start = g_off[node];
    const int end   = g_off[node + 1];
    const int cnt   = end - start;
    const float dd  = g_dis[node];
    const uint2* hbase = reinterpret_cast<const uint2*>(g_h);   // row = 32 uint2

    // coalesced index prefetch: lane L holds src id of edge L
    int idx = (lane < cnt) ? g_bucket[start + lane] : 0;

    // self-loop piece
    float2 a0, a1;
    {
        uint2 u = hbase[(size_t)node * 32 + lane];
        a0 = __half22float2(*reinterpret_cast<__half2*>(&u.x));
        a1 = __half22float2(*reinterpret_cast<__half2*>(&u.y));
    }

    const int m = cnt < 32 ? cnt : 32;   // warp-uniform
    int base = 0;

    // 16 independent row loads in flight (covers the modal degree in one round)
    for (; base + 16 <= m; base += 16) {
        uint2 u[16];
#pragma unroll
        for (int q = 0; q < 16; q++) {
            int s = __shfl_sync(FULL, idx, base + q);
            u[q] = hbase[(size_t)s * 32 + lane];
        }
#pragma unroll
        for (int q = 0; q < 16; q++)
            ACC2(u[q]);
    }
    if (m - base >= 8) {
        uint2 u[8];
#pragma unroll
        for (int q = 0; q < 8; q++) {
            int s = __shfl_sync(FULL, idx, base + q);
            u[q] = hbase[(size_t)s * 32 + lane];
        }
#pragma unroll
        for (int q = 0; q < 8; q++)
            ACC2(u[q]);
        base += 8;
    }
    if (m - base >= 4) {
        uint2 u[4];
#pragma unroll
        for (int q = 0; q < 4; q++) {
            int s = __shfl_sync(FULL, idx, base + q);
            u[q] = hbase[(size_t)s * 32 + lane];
        }
#pragma unroll
        for (int q = 0; q < 4; q++)
            ACC2(u[q]);
        base += 4;
    }
    for (; base < m; base++) {           // warp-uniform, no predication
        int s0 = __shfl_sync(FULL, idx, base);
        uint2 u0 = hbase[(size_t)s0 * 32 + lane];
        ACC2(u0);
    }
    // rare tail: degree > 32 (uniform scalar load, broadcast to all lanes)
    for (int j = start + 32; j < end; j++) {
        int s0 = g_bucket[j];
        uint2 u0 = hbase[(size_t)s0 * 32 + lane];
        ACC2(u0);
    }

    const float coef = 0.125f;  // sqrt(2/128)
    float4 v;
    v.x = coef * fmaxf(dd * a0.x, 0.f);
    v.y = coef * fmaxf(dd * a0.y, 0.f);
    v.z = coef * fmaxf(dd * a1.x, 0.f);
    v.w = coef * fmaxf(dd * a1.y, 0.f);
    *reinterpret_cast<float4*>(&out[(size_t)node * D + lane * 4]) = v;
}

// ---------------- resources created before any harness checkpoint ----------
struct KLResources {
    cudaStream_t s2, s3;
    cudaEvent_t ev_fork, ev_hist, ev_dis, ev_csr, ev_join, ev_zero;
    KLResources() {
        cudaStreamCreateWithFlags(&s2, cudaStreamNonBlocking);
        cudaStreamCreateWithFlags(&s3, cudaStreamNonBlocking);
        cudaEventCreateWithFlags(&ev_fork, cudaEventDisableTiming);
        cudaEventCreateWithFlags(&ev_hist, cudaEventDisableTiming);
        cudaEventCreateWithFlags(&ev_dis,  cudaEventDisableTiming);
        cudaEventCreateWithFlags(&ev_csr,  cudaEventDisableTiming);
        cudaEventCreateWithFlags(&ev_join, cudaEventDisableTiming);
        cudaEventCreateWithFlags(&ev_zero, cudaEventDisableTiming);
        cudaFuncSetAttribute(gemm_mma_kernel,
                             cudaFuncAttributeMaxDynamicSharedMemorySize,
                             2 * 128 * 68 * 4);
    }
};
static KLResources g_res;

extern "C" void kernel_launch(void* const* d_in, const int* in_sizes, int n_in,
                              void* d_out, int out_size)
{
    const float* x  = (const float*)d_in[0];
    const int*   ei = (const int*)d_in[1];   // int32: JAX x64 disabled
    const float* W  = (const float*)d_in[2];
    const float* b  = (const float*)d_in[3];
    float* out = (float*)d_out;

    const int GEMM_SMEM = 2 * 128 * 68 * 4;  // 69632 B

    // fork: GEMM on s2 (depends on nothing)
    cudaEventRecord(g_res.ev_fork, 0);
    cudaStreamWaitEvent(g_res.s2, g_res.ev_fork, 0);
    cudaStreamWaitEvent(g_res.s3, g_res.ev_fork, 0);
    gemm_mma_kernel<<<(N_NODES + 127) / 128, 256, GEMM_SMEM, g_res.s2>>>(x, W, b);

    // main: hist -> scan -> fill   (g_cnt/g_deg are zero from previous call)
    hist_kernel<<<(N_EDGES + 255) / 256, 256>>>(ei);
    cudaEventRecord(g_res.ev_hist, 0);
    scan_p1<<<100, 256>>>();
    scan_p3<<<100, 256>>>();
    cudaEventRecord(g_res.ev_csr, 0);   // g_cnt no longer needed after this
    fill_kernel<<<(N_EDGES + 255) / 256, 256>>>(ei);

    // s3: dis after hist (parallel with scan/fill)
    cudaStreamWaitEvent(g_res.s3, g_res.ev_hist, 0);
    dis_kernel<<<(N_NODES + 255) / 256, 256, 0, g_res.s3>>>();
    cudaEventRecord(g_res.ev_dis, g_res.s3);

    // s2: in-place scale after GEMM + dis; then trailing zero
    cudaStreamWaitEvent(g_res.s2, g_res.ev_dis, 0);
    scale_kernel<<<(N_NODES * 16 + 255) / 256, 256, 0, g_res.s2>>>();
    cudaEventRecord(g_res.ev_join, g_res.s2);
    cudaStreamWaitEvent(g_res.s2, g_res.ev_csr, 0);
    zero_kernel<<<(N_PAD + 255) / 256, 256, 0, g_res.s2>>>();   // for next call
    cudaEventRecord(g_res.ev_zero, g_res.s2);

    // join: gather needs CSR (main) + h' (s2); zero overlaps with gather
    cudaStreamWaitEvent(0, g_res.ev_join, 0);
    gather_kernel<<<(N_NODES + 7) / 8, 256>>>(out);
    cudaStreamWaitEvent(0, g_res.ev_zero, 0);   // rejoin s2 before capture end
}

// round 16
// speedup vs baseline: 1.1025x; 1.1025x over previous
#include <cuda_runtime.h>
#include <cuda_fp16.h>
#include <cstdint>

#define N_NODES 100000
#define N_EDGES 1600000
#define D 128
#define N_PAD 102400   // 100 blocks * 1024 ints, zero-padded tail

// Scratch (no cudaMalloc allowed). g_cnt/g_deg are zero at entry of every
// call: BSS init covers call 1, the trailing zero_kernel covers the rest.
__device__ __align__(16) __half2 g_h[(size_t)N_NODES * (D / 2)];  // feats, fp16
__device__ __align__(16) int   g_deg[N_NODES];
__device__ __align__(16) float g_dis[N_NODES];
__device__ __align__(16) int   g_cnt[N_PAD];
__device__ __align__(16) int   g_off[N_PAD + 4];
__device__ __align__(16) int   g_cursor[N_PAD];
__device__ __align__(16) int   g_bucket[N_EDGES];
__device__ __align__(16) int   g_bsum[128];

// ---------------- zero counters (runs at END of call, for the next one) ----
__global__ __launch_bounds__(256) void zero_kernel()
{
    int i = blockIdx.x * 256 + threadIdx.x;
    if (i < N_PAD) g_cnt[i] = 0;
    if (i < N_NODES) g_deg[i] = 0;
}

// ---------------- fused histogram: deg over src, cnt over dst --------------
__global__ __launch_bounds__(256) void hist_kernel(const int* __restrict__ ei)
{
    int e = blockIdx.x * 256 + threadIdx.x;
    if (e < N_EDGES) {
        atomicAdd(&g_deg[ei[e]], 1);
        atomicAdd(&g_cnt[ei[N_EDGES + e]], 1);
    }
}

// ---------------- dis = rsqrt(deg + 1 self loop) ----------------
__global__ __launch_bounds__(256) void dis_kernel()
{
    int i = blockIdx.x * 256 + threadIdx.x;
    if (i < N_NODES) {
        g_dis[i] = rsqrtf((float)(g_deg[i] + 1));
    }
}

// ---------------- 2-phase exclusive scan over g_cnt ------------------------
// Phase 1: 100 blocks x 256 thr; each block sums 1024 ints -> g_bsum[blk]
__global__ __launch_bounds__(256) void scan_p1()
{
    __shared__ int wsum[8];
    const int tid = threadIdx.x;
    int4 v = reinterpret_cast<const int4*>(g_cnt)[blockIdx.x * 256 + tid];
    int s = v.x + v.y + v.z + v.w;
#pragma unroll
    for (int o = 16; o > 0; o >>= 1)
        s += __shfl_down_sync(0xffffffffu, s, o);
    if ((tid & 31) == 0) wsum[tid >> 5] = s;
    __syncthreads();
    if (tid < 8) {
        int t = wsum[tid];
#pragma unroll
        for (int o = 4; o > 0; o >>= 1)
            t += __shfl_down_sync(0xffu, t, o);
        if (tid == 0) g_bsum[blockIdx.x] = t;
    }
}

// Phase 2: local scan + inline block-base reduction over g_bsum
__global__ __launch_bounds__(256) void scan_p3()
{
    __shared__ int wbase[8];
    __shared__ int red[4];
    const int tid  = threadIdx.x;
    const int lane = tid & 31;
    const int wid  = tid >> 5;
    const int gi   = blockIdx.x * 256 + tid;
    const unsigned FULL = 0xffffffffu;

    int4 v = reinterpret_cast<const int4*>(g_cnt)[gi];
    int tot = v.x + v.y + v.z + v.w;

    // warp inclusive scan of per-thread totals
    int incl = tot;
#pragma unroll
    for (int o = 1; o < 32; o <<= 1) {
        int t = __shfl_up_sync(FULL, incl, o);
        if (lane >= o) incl += t;
    }
    if (lane == 31) wbase[wid] = incl;

    // block base = sum of g_bsum[k] for k < blockIdx.x (first 128 threads)
    int r = 0;
    if (tid < 128) r = (tid < blockIdx.x) ? g_bsum[tid] : 0;
#pragma unroll
    for (int o = 16; o > 0; o >>= 1)
        r += __shfl_down_sync(FULL, r, o);
    if (tid < 128 && lane == 0) red[wid] = r;
    __syncthreads();

    if (tid < 8) {
        int t = wbase[tid];
        int e = 0;
        for (int k = 0; k < 8; k++) {
            int vk = __shfl_sync(0xffu, t, k);
            if (tid > k) e += vk;
        }
        wbase[tid] = e;
    }
    __syncthreads();

    int base = (red[0] + red[1] + red[2] + red[3]) + wbase[wid] + (incl - tot);
    int4 o;
    o.x = base;
    o.y = base + v.x;
    o.z = base + v.x + v.y;
    o.w = base + v.x + v.y + v.z;
    reinterpret_cast<int4*>(g_off)[gi]    = o;
    reinterpret_cast<int4*>(g_cursor)[gi] = o;
}

// ---------------- tf32 helpers ----------------
__device__ __forceinline__ unsigned f2tf32(float f) {
    unsigned u;
    asm("cvt.rna.tf32.f32 %0, %1;" : "=r"(u) : "f"(f));
    return u;
}
__device__ __forceinline__ void mma_tf32(
    float& d0, float& d1, float& d2, float& d3,
    unsigned a0, unsigned a1, unsigned a2, unsigned a3,
    unsigned b0, unsigned b1)
{
    asm volatile(
        "mma.sync.aligned.m16n8k8.row.col.f32.tf32.tf32.f32 "
        "{%0,%1,%2,%3}, {%4,%5,%6,%7}, {%8,%9}, {%0,%1,%2,%3};"
        : "+f"(d0), "+f"(d1), "+f"(d2), "+f"(d3)
        : "r"(a0), "r"(a1), "r"(a2), "r"(a3), "r"(b0), "r"(b1));
}

// ---------------- GEMM via tf32 tensor cores -> fp16 raw h ------------------
#define KC 64
#define XS(r, k) smem_u[(r) * 68 + (k)]
#define WS(n, k) smem_u[128 * 68 + (n) * 68 + (k)]

__global__ __launch_bounds__(256, 2) void gemm_mma_kernel(
    const float* __restrict__ x, const float* __restrict__ W,
    const float* __restrict__ b)
{
    extern __shared__ unsigned smem_u[];   // 69632 B

    const int tid  = threadIdx.x;
    const int lane = tid & 31;
    const int warp = tid >> 5;
    const int r    = lane >> 2;
    const int c    = lane & 3;
    const int lrow = warp * 16;
    const int m0   = blockIdx.x * 128;

    float acc[16][4];
#pragma unroll
    for (int t = 0; t < 16; t++)
#pragma unroll
        for (int j = 0; j < 4; j++) acc[t][j] = 0.f;

#pragma unroll
    for (int chunk = 0; chunk < 2; chunk++) {
        const int kc = chunk * KC;
#pragma unroll
        for (int i = 0; i < 8; i++) {
            int f = tid + i * 256;
            int row = f >> 4;
            int kq  = f & 15;
            int grow = m0 + row;
            if (grow >= N_NODES) grow = N_NODES - 1;
            float4 xv = *reinterpret_cast<const float4*>(&x[(size_t)grow * D + kc + kq * 4]);
            uint4 xu = make_uint4(f2tf32(xv.x), f2tf32(xv.y), f2tf32(xv.z), f2tf32(xv.w));
            *reinterpret_cast<uint4*>(&XS(row, kq * 4)) = xu;
            float4 wv = *reinterpret_cast<const float4*>(&W[(size_t)row * D + kc + kq * 4]);
            uint4 wu = make_uint4(f2tf32(wv.x), f2tf32(wv.y), f2tf32(wv.z), f2tf32(wv.w));
            *reinterpret_cast<uint4*>(&WS(row, kq * 4)) = wu;
        }
        __syncthreads();

#pragma unroll
        for (int s = 0; s < 8; s++) {
            unsigned a0 = XS(lrow + r,     s * 8 + c);
            unsigned a1 = XS(lrow + r + 8, s * 8 + c);
            unsigned a2 = XS(lrow + r,     s * 8 + c + 4);
            unsigned a3 = XS(lrow + r + 8, s * 8 + c + 4);
#pragma unroll
            for (int t = 0; t < 16; t++) {
                unsigned b0 = WS(t * 8 + r, s * 8 + c);
                unsigned b1 = WS(t * 8 + r, s * 8 + c + 4);
                mma_tf32(acc[t][0], acc[t][1], acc[t][2], acc[t][3],
                         a0, a1, a2, a3, b0, b1);
            }
        }
        __syncthreads();
    }

    // epilogue: fp16 raw h (dis applied later, in place)
    const int row_a = m0 + lrow + r;
    const int row_b = row_a + 8;
#pragma unroll
    for (int t = 0; t < 16; t++) {
        int col0 = t * 8 + c * 2;
        float2 bias = *reinterpret_cast<const float2*>(&b[col0]);
        if (row_a < N_NODES) {
            g_h[(size_t)row_a * 64 + t * 4 + c] =
                __floats2half2_rn(acc[t][0] + bias.x, acc[t][1] + bias.y);
        }
        if (row_b < N_NODES) {
            g_h[(size_t)row_b * 64 + t * 4 + c] =
                __floats2half2_rn(acc[t][2] + bias.x, acc[t][3] + bias.y);
        }
    }
}

// ---------------- scale (in place): g_h[row] *= dis[row] --------------------
// A row is 128 halfs = 256 B = 16 uint4  -> N_NODES*16 threads.
__global__ __launch_bounds__(256) void scale_kernel()
{
    int gid = blockIdx.x * 256 + threadIdx.x;
    int row = gid >> 4, q = gid & 15;           // q: uint4 index within row
    if (row >= N_NODES) return;
    float dd = g_dis[row];
    uint4* p = reinterpret_cast<uint4*>(g_h) + (size_t)row * 16 + q;
    uint4 u = *p;
    __half2* hp = reinterpret_cast<__half2*>(&u);
#pragma unroll
    for (int k = 0; k < 4; k++) {
        float2 f = __half22float2(hp[k]);
        hp[k] = __floats2half2_rn(dd * f.x, dd * f.y);
    }
    *p = u;
}

// ---------------- bucket fill: group src ids by dst -------------------------
__global__ __launch_bounds__(256) void fill_kernel(const int* __restrict__ ei)
{
    int e = blockIdx.x * 256 + threadIdx.x;
    if (e < N_EDGES) {
        int src = ei[e];
        int dst = ei[N_EDGES + e];
        int pos = atomicAdd(&g_cursor[dst], 1);
        g_bucket[pos] = src;
    }
}

// ---------------- gather: warp per node, warp per edge, 8-deep batches ------
// (R13 structure — 8 loads in flight is the measured sweet spot; 16-deep
//  regressed twice, R10 and R15.)
#define ACC2(U) do {                                                          \
    float2 f_;                                                                \
    f_ = __half22float2(*reinterpret_cast<__half2*>(&(U).x)); a0.x += f_.x; a0.y += f_.y; \
    f_ = __half22float2(*reinterpret_cast<__half2*>(&(U).y)); a1.x += f_.x; a1.y += f_.y; \
} while (0)

__global__ __launch_bounds__(256) void gather_kernel(float* __restrict__ out)
{
    const int node = blockIdx.x * 8 + (threadIdx.x >> 5);
    if (node >= N_NODES) return;
    const int lane = threadIdx.x & 31;
    const unsigned FULL = 0xffffffffu;

    const int start = g_off[node];
    const int end   = g_off[node + 1];
    const int cnt   = end - start;
    const float dd  = g_dis[node];
    const uint2* hbase = reinterpret_cast<const uint2*>(g_h);   // row = 32 uint2

    // coalesced index prefetch: lane L holds src id of edge L
    int idx = (lane < cnt) ? g_bucket[start + lane] : 0;

    // self-loop piece
    float2 a0, a1;
    {
        uint2 u = hbase[(size_t)node * 32 + lane];
        a0 = __half22float2(*reinterpret_cast<__half2*>(&u.x));
        a1 = __half22float2(*reinterpret_cast<__half2*>(&u.y));
    }

    const int m = cnt < 32 ? cnt : 32;   // warp-uniform
    int base = 0;

    // 8 independent row loads in flight
    for (; base + 8 <= m; base += 8) {
        int s[8];
#pragma unroll
        for (int q = 0; q < 8; q++)
            s[q] = __shfl_sync(FULL, idx, base + q);
        uint2 u[8];
#pragma unroll
        for (int q = 0; q < 8; q++)
            u[q] = hbase[(size_t)s[q] * 32 + lane];
#pragma unroll
        for (int q = 0; q < 8; q++)
            ACC2(u[q]);
    }
    if (m - base >= 4) {
        int s[4];
#pragma unroll
        for (int q = 0; q < 4; q++)
            s[q] = __shfl_sync(FULL, idx, base + q);
        uint2 u[4];
#pragma unroll
        for (int q = 0; q < 4; q++)
            u[q] = hbase[(size_t)s[q] * 32 + lane];
#pragma unroll
        for (int q = 0; q < 4; q++)
            ACC2(u[q]);
        base += 4;
    }
    for (; base < m; base++) {           // warp-uniform, no predication
        int s0 = __shfl_sync(FULL, idx, base);
        uint2 u0 = hbase[(size_t)s0 * 32 + lane];
        ACC2(u0);
    }
    // rare tail: degree > 32 (uniform scalar load, broadcast to all lanes)
    for (int j = start + 32; j < end; j++) {
        int s0 = g_bucket[j];
        uint2 u0 = hbase[(size_t)s0 * 32 + lane];
        ACC2(u0);
    }

    const float coef = 0.125f;  // sqrt(2/128)
    float4 v;
    v.x = coef * fmaxf(dd * a0.x, 0.f);
    v.y = coef * fmaxf(dd * a0.y, 0.f);
    v.z = coef * fmaxf(dd * a1.x, 0.f);
    v.w = coef * fmaxf(dd * a1.y, 0.f);
    *reinterpret_cast<float4*>(&out[(size_t)node * D + lane * 4]) = v;
}

// ---------------- resources created before any harness checkpoint ----------
struct KLResources {
    cudaStream_t s2, s3;
    cudaEvent_t ev_fork, ev_hist, ev_dis, ev_csr, ev_join, ev_zero;
    KLResources() {
        cudaStreamCreateWithFlags(&s2, cudaStreamNonBlocking);
        cudaStreamCreateWithFlags(&s3, cudaStreamNonBlocking);
        cudaEventCreateWithFlags(&ev_fork, cudaEventDisableTiming);
        cudaEventCreateWithFlags(&ev_hist, cudaEventDisableTiming);
        cudaEventCreateWithFlags(&ev_dis,  cudaEventDisableTiming);
        cudaEventCreateWithFlags(&ev_csr,  cudaEventDisableTiming);
        cudaEventCreateWithFlags(&ev_join, cudaEventDisableTiming);
        cudaEventCreateWithFlags(&ev_zero, cudaEventDisableTiming);
        cudaFuncSetAttribute(gemm_mma_kernel,
                             cudaFuncAttributeMaxDynamicSharedMemorySize,
                             2 * 128 * 68 * 4);
    }
};
static KLResources g_res;

extern "C" void kernel_launch(void* const* d_in, const int* in_sizes, int n_in,
                              void* d_out, int out_size)
{
    const float* x  = (const float*)d_in[0];
    const int*   ei = (const int*)d_in[1];   // int32: JAX x64 disabled
    const float* W  = (const float*)d_in[2];
    const float* b  = (const float*)d_in[3];
    float* out = (float*)d_out;

    const int GEMM_SMEM = 2 * 128 * 68 * 4;  // 69632 B

    // fork: GEMM on s2 (depends on nothing)
    cudaEventRecord(g_res.ev_fork, 0);
    cudaStreamWaitEvent(g_res.s2, g_res.ev_fork, 0);
    cudaStreamWaitEvent(g_res.s3, g_res.ev_fork, 0);
    gemm_mma_kernel<<<(N_NODES + 127) / 128, 256, GEMM_SMEM, g_res.s2>>>(x, W, b);

    // main: hist -> scan -> fill   (g_cnt/g_deg are zero from previous call)
    hist_kernel<<<(N_EDGES + 255) / 256, 256>>>(ei);
    cudaEventRecord(g_res.ev_hist, 0);
    scan_p1<<<100, 256>>>();
    scan_p3<<<100, 256>>>();
    cudaEventRecord(g_res.ev_csr, 0);   // g_cnt no longer needed after this
    fill_kernel<<<(N_EDGES + 255) / 256, 256>>>(ei);

    // s3: dis after hist (parallel with scan/fill)
    cudaStreamWaitEvent(g_res.s3, g_res.ev_hist, 0);
    dis_kernel<<<(N_NODES + 255) / 256, 256, 0, g_res.s3>>>();
    cudaEventRecord(g_res.ev_dis, g_res.s3);

    // s2: in-place scale after GEMM + dis; then trailing zero
    cudaStreamWaitEvent(g_res.s2, g_res.ev_dis, 0);
    scale_kernel<<<(N_NODES * 16 + 255) / 256, 256, 0, g_res.s2>>>();
    cudaEventRecord(g_res.ev_join, g_res.s2);
    cudaStreamWaitEvent(g_res.s2, g_res.ev_csr, 0);
    zero_kernel<<<(N_PAD + 255) / 256, 256, 0, g_res.s2>>>();   // for next call
    cudaEventRecord(g_res.ev_zero, g_res.s2);

    // join: gather needs CSR (main) + h' (s2); zero overlaps with gather
    cudaStreamWaitEvent(0, g_res.ev_join, 0);
    gather_kernel<<<(N_NODES + 7) / 8, 256>>>(out);
    cudaStreamWaitEvent(0, g_res.ev_zero, 0);   // rejoin s2 before capture end
}

// round 17
// speedup vs baseline: 1.1215x; 1.0172x over previous
#include <cuda_runtime.h>
#include <cuda_fp16.h>
#include <cstdint>

#define N_NODES 100000
#define N_EDGES 1600000
#define D 128
#define N_PAD 102400   // 100 blocks * 1024 ints, zero-padded tail

// Scratch (no cudaMalloc allowed). g_cnt/g_deg are zero at entry of every
// call: BSS init covers call 1, the trailing zero_kernel covers the rest.
__device__ __align__(16) __half2 g_h[(size_t)N_NODES * (D / 2)];  // feats, fp16
__device__ __align__(16) int   g_deg[N_NODES];
__device__ __align__(16) float g_dis[N_NODES];
__device__ __align__(16) int   g_cnt[N_PAD];
__device__ __align__(16) int   g_off[N_PAD + 4];
__device__ __align__(16) int   g_cursor[N_PAD];
__device__ __align__(16) int   g_bucket[N_EDGES];
__device__ __align__(16) int   g_bsum[128];

// ---------------- zero counters (runs at END of call, for the next one) ----
__global__ __launch_bounds__(256) void zero_kernel()
{
    int i = blockIdx.x * 256 + threadIdx.x;
    if (i < N_PAD) g_cnt[i] = 0;
    if (i < N_NODES) g_deg[i] = 0;
}

// ---------------- fused histogram: 4 edges per thread (int4 loads) ---------
__global__ __launch_bounds__(256) void hist_kernel(const int* __restrict__ ei)
{
    int i = blockIdx.x * 256 + threadIdx.x;     // N_EDGES/4 threads
    if (i < N_EDGES / 4) {
        int4 s4 = reinterpret_cast<const int4*>(ei)[i];
        int4 d4 = reinterpret_cast<const int4*>(ei + N_EDGES)[i];
        atomicAdd(&g_deg[s4.x], 1);
        atomicAdd(&g_deg[s4.y], 1);
        atomicAdd(&g_deg[s4.z], 1);
        atomicAdd(&g_deg[s4.w], 1);
        atomicAdd(&g_cnt[d4.x], 1);
        atomicAdd(&g_cnt[d4.y], 1);
        atomicAdd(&g_cnt[d4.z], 1);
        atomicAdd(&g_cnt[d4.w], 1);
    }
}

// ---------------- dis = rsqrt(deg + 1 self loop) ----------------
__global__ __launch_bounds__(256) void dis_kernel()
{
    int i = blockIdx.x * 256 + threadIdx.x;
    if (i < N_NODES) {
        g_dis[i] = rsqrtf((float)(g_deg[i] + 1));
    }
}

// ---------------- 2-phase exclusive scan over g_cnt ------------------------
__global__ __launch_bounds__(256) void scan_p1()
{
    __shared__ int wsum[8];
    const int tid = threadIdx.x;
    int4 v = reinterpret_cast<const int4*>(g_cnt)[blockIdx.x * 256 + tid];
    int s = v.x + v.y + v.z + v.w;
#pragma unroll
    for (int o = 16; o > 0; o >>= 1)
        s += __shfl_down_sync(0xffffffffu, s, o);
    if ((tid & 31) == 0) wsum[tid >> 5] = s;
    __syncthreads();
    if (tid < 8) {
        int t = wsum[tid];
#pragma unroll
        for (int o = 4; o > 0; o >>= 1)
            t += __shfl_down_sync(0xffu, t, o);
        if (tid == 0) g_bsum[blockIdx.x] = t;
    }
}

__global__ __launch_bounds__(256) void scan_p3()
{
    __shared__ int wbase[8];
    __shared__ int red[4];
    const int tid  = threadIdx.x;
    const int lane = tid & 31;
    const int wid  = tid >> 5;
    const int gi   = blockIdx.x * 256 + tid;
    const unsigned FULL = 0xffffffffu;

    int4 v = reinterpret_cast<const int4*>(g_cnt)[gi];
    int tot = v.x + v.y + v.z + v.w;

    int incl = tot;
#pragma unroll
    for (int o = 1; o < 32; o <<= 1) {
        int t = __shfl_up_sync(FULL, incl, o);
        if (lane >= o) incl += t;
    }
    if (lane == 31) wbase[wid] = incl;

    int r = 0;
    if (tid < 128) r = (tid < blockIdx.x) ? g_bsum[tid] : 0;
#pragma unroll
    for (int o = 16; o > 0; o >>= 1)
        r += __shfl_down_sync(FULL, r, o);
    if (tid < 128 && lane == 0) red[wid] = r;
    __syncthreads();

    if (tid < 8) {
        int t = wbase[tid];
        int e = 0;
        for (int k = 0; k < 8; k++) {
            int vk = __shfl_sync(0xffu, t, k);
            if (tid > k) e += vk;
        }
        wbase[tid] = e;
    }
    __syncthreads();

    int base = (red[0] + red[1] + red[2] + red[3]) + wbase[wid] + (incl - tot);
    int4 o;
    o.x = base;
    o.y = base + v.x;
    o.z = base + v.x + v.y;
    o.w = base + v.x + v.y + v.z;
    reinterpret_cast<int4*>(g_off)[gi]    = o;
    reinterpret_cast<int4*>(g_cursor)[gi] = o;
}

// ---------------- tf32 helpers ----------------
__device__ __forceinline__ unsigned f2tf32(float f) {
    unsigned u;
    asm("cvt.rna.tf32.f32 %0, %1;" : "=r"(u) : "f"(f));
    return u;
}
__device__ __forceinline__ void mma_tf32(
    float& d0, float& d1, float& d2, float& d3,
    unsigned a0, unsigned a1, unsigned a2, unsigned a3,
    unsigned b0, unsigned b1)
{
    asm volatile(
        "mma.sync.aligned.m16n8k8.row.col.f32.tf32.tf32.f32 "
        "{%0,%1,%2,%3}, {%4,%5,%6,%7}, {%8,%9}, {%0,%1,%2,%3};"
        : "+f"(d0), "+f"(d1), "+f"(d2), "+f"(d3)
        : "r"(a0), "r"(a1), "r"(a2), "r"(a3), "r"(b0), "r"(b1));
}

// ---------------- GEMM via tf32 tensor cores -> fp16 raw h ------------------
// Warp tile 32 rows x 64 cols (2 m-tiles x 8 n-tiles): 24 LDS per 16 MMAs
// instead of 36 (old 16x128 tile) — smem crossbar was the bottleneck.
#define KC 64
#define XS(r, k) smem_u[(r) * 68 + (k)]
#define WS(n, k) smem_u[128 * 68 + (n) * 68 + (k)]

__global__ __launch_bounds__(256, 2) void gemm_mma_kernel(
    const float* __restrict__ x, const float* __restrict__ W,
    const float* __restrict__ b)
{
    extern __shared__ unsigned smem_u[];   // 69632 B

    const int tid  = threadIdx.x;
    const int lane = tid & 31;
    const int warp = tid >> 5;            // 0..7
    const int wm   = warp >> 1;           // 0..3: row group (32 rows)
    const int wn   = warp & 1;            // 0..1: col group (64 cols)
    const int r    = lane >> 2;           // 0..7
    const int c    = lane & 3;            // 0..3
    const int m0   = blockIdx.x * 128;

    float acc[2][8][4];                   // [m-tile][n-tile][frag]
#pragma unroll
    for (int mt = 0; mt < 2; mt++)
#pragma unroll
        for (int nt = 0; nt < 8; nt++)
#pragma unroll
            for (int j = 0; j < 4; j++) acc[mt][nt][j] = 0.f;

#pragma unroll
    for (int chunk = 0; chunk < 2; chunk++) {
        const int kc = chunk * KC;
#pragma unroll
        for (int i = 0; i < 8; i++) {
            int f = tid + i * 256;
            int row = f >> 4;
            int kq  = f & 15;
            int grow = m0 + row;
            if (grow >= N_NODES) grow = N_NODES - 1;
            float4 xv = *reinterpret_cast<const float4*>(&x[(size_t)grow * D + kc + kq * 4]);
            uint4 xu = make_uint4(f2tf32(xv.x), f2tf32(xv.y), f2tf32(xv.z), f2tf32(xv.w));
            *reinterpret_cast<uint4*>(&XS(row, kq * 4)) = xu;
            float4 wv = *reinterpret_cast<const float4*>(&W[(size_t)row * D + kc + kq * 4]);
            uint4 wu = make_uint4(f2tf32(wv.x), f2tf32(wv.y), f2tf32(wv.z), f2tf32(wv.w));
            *reinterpret_cast<uint4*>(&WS(row, kq * 4)) = wu;
        }
        __syncthreads();

#pragma unroll
        for (int s = 0; s < 8; s++) {
            unsigned a[2][4];
#pragma unroll
            for (int mt = 0; mt < 2; mt++) {
                int mrow = wm * 32 + mt * 16;
                a[mt][0] = XS(mrow + r,     s * 8 + c);
                a[mt][1] = XS(mrow + r + 8, s * 8 + c);
                a[mt][2] = XS(mrow + r,     s * 8 + c + 4);
                a[mt][3] = XS(mrow + r + 8, s * 8 + c + 4);
            }
#pragma unroll
            for (int nt = 0; nt < 8; nt++) {
                int nrow = wn * 64 + nt * 8 + r;
                unsigned b0 = WS(nrow, s * 8 + c);
                unsigned b1 = WS(nrow, s * 8 + c + 4);
#pragma unroll
                for (int mt = 0; mt < 2; mt++)
                    mma_tf32(acc[mt][nt][0], acc[mt][nt][1],
                             acc[mt][nt][2], acc[mt][nt][3],
                             a[mt][0], a[mt][1], a[mt][2], a[mt][3], b0, b1);
            }
        }
        __syncthreads();
    }

    // epilogue: fp16 raw h (dis applied later, in place)
#pragma unroll
    for (int mt = 0; mt < 2; mt++) {
        const int row_a = m0 + wm * 32 + mt * 16 + r;
        const int row_b = row_a + 8;
#pragma unroll
        for (int nt = 0; nt < 8; nt++) {
            int col0 = wn * 64 + nt * 8 + c * 2;
            float2 bias = *reinterpret_cast<const float2*>(&b[col0]);
            if (row_a < N_NODES) {
                g_h[(size_t)row_a * 64 + (col0 >> 1)] =
                    __floats2half2_rn(acc[mt][nt][0] + bias.x, acc[mt][nt][1] + bias.y);
            }
            if (row_b < N_NODES) {
                g_h[(size_t)row_b * 64 + (col0 >> 1)] =
                    __floats2half2_rn(acc[mt][nt][2] + bias.x, acc[mt][nt][3] + bias.y);
            }
        }
    }
}

// ---------------- scale (in place): g_h[row] *= dis[row] --------------------
// A row is 128 halfs = 256 B = 16 uint4  -> N_NODES*16 threads.
__global__ __launch_bounds__(256) void scale_kernel()
{
    int gid = blockIdx.x * 256 + threadIdx.x;
    int row = gid >> 4, q = gid & 15;           // q: uint4 index within row
    if (row >= N_NODES) return;
    float dd = g_dis[row];
    uint4* p = reinterpret_cast<uint4*>(g_h) + (size_t)row * 16 + q;
    uint4 u = *p;
    __half2* hp = reinterpret_cast<__half2*>(&u);
#pragma unroll
    for (int k = 0; k < 4; k++) {
        float2 f = __half22float2(hp[k]);
        hp[k] = __floats2half2_rn(dd * f.x, dd * f.y);
    }
    *p = u;
}

// ---------------- bucket fill: group src ids by dst -------------------------
__global__ __launch_bounds__(256) void fill_kernel(const int* __restrict__ ei)
{
    int e = blockIdx.x * 256 + threadIdx.x;
    if (e < N_EDGES) {
        int src = ei[e];
        int dst = ei[N_EDGES + e];
        int pos = atomicAdd(&g_cursor[dst], 1);
        g_bucket[pos] = src;
    }
}

// ---------------- gather: warp per node, warp per edge, 8-deep batches ------
#define ACC2(U) do {                                                          \
    float2 f_;                                                                \
    f_ = __half22float2(*reinterpret_cast<__half2*>(&(U).x)); a0.x += f_.x; a0.y += f_.y; \
    f_ = __half22float2(*reinterpret_cast<__half2*>(&(U).y)); a1.x += f_.x; a1.y += f_.y; \
} while (0)

__global__ __launch_bounds__(256) void gather_kernel(float* __restrict__ out)
{
    const int node = blockIdx.x * 8 + (threadIdx.x >> 5);
    if (node >= N_NODES) return;
    const int lane = threadIdx.x & 31;
    const unsigned FULL = 0xffffffffu;

    const int start = g_off[node];
    const int end   = g_off[node + 1];
    const int cnt   = end - start;
    const float dd  = g_dis[node];
    const uint2* hbase = reinterpret_cast<const uint2*>(g_h);   // row = 32 uint2

    int idx = (lane < cnt) ? g_bucket[start + lane] : 0;

    float2 a0, a1;
    {
        uint2 u = hbase[(size_t)node * 32 + lane];
        a0 = __half22float2(*reinterpret_cast<__half2*>(&u.x));
        a1 = __half22float2(*reinterpret_cast<__half2*>(&u.y));
    }

    const int m = cnt < 32 ? cnt : 32;   // warp-uniform
    int base = 0;

    for (; base + 8 <= m; base += 8) {
        int s[8];
#pragma unroll
        for (int q = 0; q < 8; q++)
            s[q] = __shfl_sync(FULL, idx, base + q);
        uint2 u[8];
#pragma unroll
        for (int q = 0; q < 8; q++)
            u[q] = hbase[(size_t)s[q] * 32 + lane];
#pragma unroll
        for (int q = 0; q < 8; q++)
            ACC2(u[q]);
    }
    if (m - base >= 4) {
        int s[4];
#pragma unroll
        for (int q = 0; q < 4; q++)
            s[q] = __shfl_sync(FULL, idx, base + q);
        uint2 u[4];
#pragma unroll
        for (int q = 0; q < 4; q++)
            u[q] = hbase[(size_t)s[q] * 32 + lane];
#pragma unroll
        for (int q = 0; q < 4; q++)
            ACC2(u[q]);
        base += 4;
    }
    for (; base < m; base++) {
        int s0 = __shfl_sync(FULL, idx, base);
        uint2 u0 = hbase[(size_t)s0 * 32 + lane];
        ACC2(u0);
    }
    for (int j = start + 32; j < end; j++) {
        int s0 = g_bucket[j];
        uint2 u0 = hbase[(size_t)s0 * 32 + lane];
        ACC2(u0);
    }

    const float coef = 0.125f;  // sqrt(2/128)
    float4 v;
    v.x = coef * fmaxf(dd * a0.x, 0.f);
    v.y = coef * fmaxf(dd * a0.y, 0.f);
    v.z = coef * fmaxf(dd * a1.x, 0.f);
    v.w = coef * fmaxf(dd * a1.y, 0.f);
    *reinterpret_cast<float4*>(&out[(size_t)node * D + lane * 4]) = v;
}

// ---------------- resources created before any harness checkpoint ----------
struct KLResources {
    cudaStream_t s2, s3;
    cudaEvent_t ev_fork, ev_hist, ev_dis, ev_csr, ev_join, ev_zero;
    KLResources() {
        cudaStreamCreateWithFlags(&s2, cudaStreamNonBlocking);
        cudaStreamCreateWithFlags(&s3, cudaStreamNonBlocking);
        cudaEventCreateWithFlags(&ev_fork, cudaEventDisableTiming);
        cudaEventCreateWithFlags(&ev_hist, cudaEventDisableTiming);
        cudaEventCreateWithFlags(&ev_dis,  cudaEventDisableTiming);
        cudaEventCreateWithFlags(&ev_csr,  cudaEventDisableTiming);
        cudaEventCreateWithFlags(&ev_join, cudaEventDisableTiming);
        cudaEventCreateWithFlags(&ev_zero, cudaEventDisableTiming);
        cudaFuncSetAttribute(gemm_mma_kernel,
                             cudaFuncAttributeMaxDynamicSharedMemorySize,
                             2 * 128 * 68 * 4);
    }
};
static KLResources g_res;

extern "C" void kernel_launch(void* const* d_in, const int* in_sizes, int n_in,
                              void* d_out, int out_size)
{
    const float* x  = (const float*)d_in[0];
    const int*   ei = (const int*)d_in[1];   // int32: JAX x64 disabled
    const float* W  = (const float*)d_in[2];
    const float* b  = (const float*)d_in[3];
    float* out = (float*)d_out;

    const int GEMM_SMEM = 2 * 128 * 68 * 4;  // 69632 B

    // fork: GEMM on s2 (depends on nothing)
    cudaEventRecord(g_res.ev_fork, 0);
    cudaStreamWaitEvent(g_res.s2, g_res.ev_fork, 0);
    cudaStreamWaitEvent(g_res.s3, g_res.ev_fork, 0);
    gemm_mma_kernel<<<(N_NODES + 127) / 128, 256, GEMM_SMEM, g_res.s2>>>(x, W, b);

    // main: hist -> scan -> fill   (g_cnt/g_deg are zero from previous call)
    hist_kernel<<<(N_EDGES / 4 + 255) / 256, 256>>>(ei);
    cudaEventRecord(g_res.ev_hist, 0);
    scan_p1<<<100, 256>>>();
    scan_p3<<<100, 256>>>();
    cudaEventRecord(g_res.ev_csr, 0);   // g_cnt no longer needed after this
    fill_kernel<<<(N_EDGES + 255) / 256, 256>>>(ei);

    // s3: dis after hist (parallel with scan/fill)
    cudaStreamWaitEvent(g_res.s3, g_res.ev_hist, 0);
    dis_kernel<<<(N_NODES + 255) / 256, 256, 0, g_res.s3>>>();
    cudaEventRecord(g_res.ev_dis, g_res.s3);

    // s2: in-place scale after GEMM + dis; then trailing zero
    cudaStreamWaitEvent(g_res.s2, g_res.ev_dis, 0);
    scale_kernel<<<(N_NODES * 16 + 255) / 256, 256, 0, g_res.s2>>>();
    cudaEventRecord(g_res.ev_join, g_res.s2);
    cudaStreamWaitEvent(g_res.s2, g_res.ev_csr, 0);
    zero_kernel<<<(N_PAD + 255) / 256, 256, 0, g_res.s2>>>();   // for next call
    cudaEventRecord(g_res.ev_zero, g_res.s2);

    // join: gather needs CSR (main) + h' (s2); zero overlaps with gather
    cudaStreamWaitEvent(0, g_res.ev_join, 0);
    gather_kernel<<<(N_NODES + 7) / 8, 256>>>(out);
    cudaStreamWaitEvent(0, g_res.ev_zero, 0);   // rejoin s2 before capture end
}